// round 1
// baseline (speedup 1.0000x reference)
#include <cuda_runtime.h>
#include <math.h>

#define NN 4096
#define FF 64
#define HH 128
#define NHD 4
#define HD 32
#define LL 3
#define CC 7
#define MAXD 96
#define HHBLK 512   // k_hh blocks (8 nodes each)
#define MBLK 64     // mean partial blocks (64 rows each)

// ---------------- device scratch (no allocations allowed) ----------------
__device__ float g_h[2][NN * HH];
__device__ float g_hh[NN * HH];
__device__ float g_sup[NN * HH];
__device__ float g_att[NN * HH];
__device__ float g_ssrc[NN * NHD];
__device__ float g_sdst[NN * NHD];
__device__ float g_Spart[HHBLK * HH];
__device__ float g_S[HH];
__device__ int   g_cols[NN * MAXD];
__device__ int   g_cnt[NN];
__device__ float g_dinv[NN];
__device__ float g_mpart[MBLK * HH];

// ---------------- 1) edge-list build: one warp per adjacency row ----------------
__global__ void k_build(const float* __restrict__ adj) {
    int warp = (blockIdx.x * blockDim.x + threadIdx.x) >> 5;
    int lane = threadIdx.x & 31;
    if (warp >= NN) return;
    const float4* row = (const float4*)(adj + (size_t)warp * NN);
    int base = warp * MAXD;
    int cnt = 0;
    for (int c0 = 0; c0 < NN / 4; c0 += 32) {
        float4 v = row[c0 + lane];
        float vals[4] = {v.x, v.y, v.z, v.w};
#pragma unroll
        for (int k = 0; k < 4; k++) {
            unsigned m = __ballot_sync(0xffffffffu, vals[k] > 0.0f);
            if (vals[k] > 0.0f) {
                int pos = cnt + __popc(m & ((1u << lane) - 1u));
                if (pos < MAXD) g_cols[base + pos] = (c0 + lane) * 4 + k;
            }
            cnt += __popc(m);
        }
    }
    if (lane == 0) {
        if (cnt > MAXD) cnt = MAXD;
        g_cnt[warp] = cnt;
        // deg = nnz(row of adj, incl diag if set) + 1 (identity)
        g_dinv[warp] = rsqrtf((float)cnt + 1.0f);
    }
}

// ---------------- 2) encoder: h0 = relu(x @ enc_W + b) ----------------
__global__ void k_enc(const float* __restrict__ x, const float* __restrict__ W,
                      const float* __restrict__ b) {
    __shared__ float xs[FF];
    int n = blockIdx.x, c = threadIdx.x;
    if (c < FF) xs[c] = x[n * FF + c];
    __syncthreads();
    float acc = b[c];
#pragma unroll 16
    for (int k = 0; k < FF; k++) acc += xs[k] * W[k * HH + c];
    g_h[0][n * HH + c] = fmaxf(acc, 0.0f);
}

// ---------------- 3) per-layer: hh = h @ W_attn + Wb ; s_src, s_dst ; S partials ----
__global__ void k_hh(int ping, const float* __restrict__ Wl,
                     const float* __restrict__ Wbl, const float* __restrict__ al) {
    __shared__ float hs[HH];
    const float* hin = g_h[ping];
    int c = threadIdx.x;
    int head = c >> 5, d = c & 31;
    float asrc = al[head * 2 * HD + d];
    float adst = al[head * 2 * HD + HD + d];
    float wb = Wbl[head * HD + d];
    const float* Wcol = Wl + head * HH * HD + d;  // stride HD over f
    float Sloc = 0.0f;
    int n0 = blockIdx.x * 8;
#pragma unroll 1
    for (int i = 0; i < 8; i++) {
        int n = n0 + i;
        __syncthreads();
        hs[c] = hin[n * HH + c];
        __syncthreads();
        float acc = wb;
#pragma unroll 16
        for (int f = 0; f < HH; f++) acc += hs[f] * Wcol[f * HD];
        g_hh[n * HH + c] = acc;
        Sloc += acc;
        float vs = acc * asrc, vd = acc * adst;
#pragma unroll
        for (int off = 16; off; off >>= 1) {
            vs += __shfl_xor_sync(0xffffffffu, vs, off);
            vd += __shfl_xor_sync(0xffffffffu, vd, off);
        }
        if (d == 0) {
            g_ssrc[n * NHD + head] = vs;
            g_sdst[n * NHD + head] = vd;
        }
    }
    g_Spart[blockIdx.x * HH + c] = Sloc;
}

__global__ void k_sred() {
    int c = threadIdx.x;
    float s = 0.0f;
    for (int b = 0; b < HHBLK; b++) s += g_Spart[b * HH + c];
    g_S[c] = s;
}

// ---------------- 4) per-layer sparse: GCN support + attention numer/denom ------
__global__ void k_sparse(int ping, const float* __restrict__ abl) {
    int n = blockIdx.x, c = threadIdx.x;
    int head = c >> 5;
    __shared__ int cols_s[MAXD];
    __shared__ float dinv_s[MAXD];
    __shared__ float w_s[MAXD * NHD];
    __shared__ float ss[NHD];
    const float* hin = g_h[ping];
    int E = g_cnt[n];
    if (c < NHD) ss[c] = g_ssrc[n * NHD + c] + abl[c];
    for (int e = c; e < E; e += HH) {
        int j = g_cols[n * MAXD + e];
        cols_s[e] = j;
        dinv_s[e] = g_dinv[j];
    }
    __syncthreads();
    for (int idx = c; idx < E * NHD; idx += HH) {
        int e = idx >> 2, h2 = idx & 3;
        w_s[idx] = expf(ss[h2] + g_sdst[cols_s[e] * NHD + h2]) - 1.0f;
    }
    __syncthreads();
    float di = g_dinv[n];
    float accg = di * hin[n * HH + c];
    float acca = g_S[c];
    float denom = (float)NN;
    for (int e = 0; e < E; e++) {
        int j = cols_s[e];
        accg += dinv_s[e] * hin[j * HH + c];
        float w = w_s[e * NHD + head];
        acca += w * g_hh[j * HH + c];
        denom += w;
    }
    g_sup[n * HH + c] = di * accg;
    g_att[n * HH + c] = acca / denom;
}

// ---------------- 5) per-layer combine: h' = relu(relu(sup@W + b) + att) -------
__global__ void k_comb(int ping, const float* __restrict__ Wl,
                       const float* __restrict__ bl) {
    __shared__ float Ws[32 * HH];   // 16KB W k-tile
    __shared__ float Ssm[32 * HH];  // 16KB support tile (32 rows)
    float* hout = g_h[ping ^ 1];
    int tid = threadIdx.x;
    int col = tid & 127, rg = tid >> 7;
    int r0 = blockIdx.x * 32;
    for (int i = tid; i < 32 * HH; i += 256) Ssm[i] = g_sup[r0 * HH + i];
    float acc[16];
#pragma unroll
    for (int i = 0; i < 16; i++) acc[i] = 0.0f;
    for (int kt = 0; kt < HH; kt += 32) {
        __syncthreads();
        for (int i = tid; i < 32 * HH; i += 256) Ws[i] = Wl[kt * HH + i];
        __syncthreads();
#pragma unroll 8
        for (int k = 0; k < 32; k++) {
            float w = Ws[k * HH + col];
#pragma unroll
            for (int i = 0; i < 16; i++)
                acc[i] += Ssm[(rg * 16 + i) * HH + kt + k] * w;
        }
    }
    float b = bl[col];
#pragma unroll
    for (int i = 0; i < 16; i++) {
        int r = r0 + rg * 16 + i;
        float v = fmaxf(acc[i] + b, 0.0f) + g_att[r * HH + col];
        hout[r * HH + col] = fmaxf(v, 0.0f);
    }
}

// ---------------- 6) classifier head + copy h to output ----------------
__global__ void k_head(int ping, const float* __restrict__ W1, const float* __restrict__ b1,
                       const float* __restrict__ W2, const float* __restrict__ b2,
                       float* __restrict__ out_logits, float* __restrict__ out_h) {
    __shared__ float hs[HH];
    __shared__ float t1[64];
    const float* hf = g_h[ping];
    int n = blockIdx.x, c = threadIdx.x;
    float hv = hf[n * HH + c];
    hs[c] = hv;
    out_h[n * HH + c] = hv;
    __syncthreads();
    if (c < 64) {
        float a = b1[c];
#pragma unroll 16
        for (int k = 0; k < HH; k++) a += hs[k] * W1[k * 64 + c];
        t1[c] = fmaxf(a, 0.0f);
    }
    __syncthreads();
    if (c < CC) {
        float a = b2[c];
#pragma unroll 16
        for (int k = 0; k < 64; k++) a += t1[k] * W2[k * CC + c];
        out_logits[n * CC + c] = a;
    }
}

// ---------------- 7) mean pooling partials + contagion head ----------------
__global__ void k_mean(int ping) {
    const float* hf = g_h[ping];
    int b = blockIdx.x, c = threadIdx.x;
    float s = 0.0f;
    for (int r = 0; r < NN / MBLK; r++) s += hf[(b * (NN / MBLK) + r) * HH + c];
    g_mpart[b * HH + c] = s;
}

__global__ void k_cont(const float* __restrict__ W1, const float* __restrict__ b1,
                       const float* __restrict__ W2, const float* __restrict__ b2,
                       float* __restrict__ out_c) {
    __shared__ float ms[HH];
    __shared__ float t1[64];
    int c = threadIdx.x;
    float s = 0.0f;
    for (int b = 0; b < MBLK; b++) s += g_mpart[b * HH + c];
    ms[c] = s * (1.0f / (float)NN);
    __syncthreads();
    if (c < 64) {
        float a = b1[c];
#pragma unroll 16
        for (int k = 0; k < HH; k++) a += ms[k] * W1[k * 64 + c];
        t1[c] = fmaxf(a, 0.0f);
    }
    __syncthreads();
    if (c == 0) {
        float a = b2[0];
        for (int k = 0; k < 64; k++) a += t1[k] * W2[k];
        out_c[0] = a;
    }
}

extern "C" void kernel_launch(void* const* d_in, const int* in_sizes, int n_in,
                              void* d_out, int out_size) {
    const float* x      = (const float*)d_in[0];
    const float* adj    = (const float*)d_in[1];
    const float* enc_W  = (const float*)d_in[2];
    const float* enc_b  = (const float*)d_in[3];
    const float* gcn_W  = (const float*)d_in[4];   // [3,128,128]
    const float* gcn_b  = (const float*)d_in[5];   // [3,128]
    const float* attn_W = (const float*)d_in[6];   // [3,4,128,32]
    const float* attn_Wb= (const float*)d_in[7];   // [3,4,32]
    const float* attn_a = (const float*)d_in[8];   // [3,4,64]
    const float* attn_ab= (const float*)d_in[9];   // [3,4]
    const float* cls_W1 = (const float*)d_in[10];
    const float* cls_b1 = (const float*)d_in[11];
    const float* cls_W2 = (const float*)d_in[12];
    const float* cls_b2 = (const float*)d_in[13];
    const float* con_W1 = (const float*)d_in[14];
    const float* con_b1 = (const float*)d_in[15];
    const float* con_W2 = (const float*)d_in[16];
    const float* con_b2 = (const float*)d_in[17];

    float* out = (float*)d_out;
    float* out_logits = out;                 // [4096,7]
    float* out_h      = out + NN * CC;       // [4096,128]
    float* out_c      = out + NN * CC + NN * HH;  // [1]

    k_build<<<NN / 8, 256>>>(adj);
    k_enc<<<NN, HH>>>(x, enc_W, enc_b);

    int ping = 0;
    for (int l = 0; l < LL; l++) {
        k_hh<<<HHBLK, HH>>>(ping, attn_W + l * NHD * HH * HD,
                            attn_Wb + l * NHD * HD, attn_a + l * NHD * 2 * HD);
        k_sred<<<1, HH>>>();
        k_sparse<<<NN, HH>>>(ping, attn_ab + l * NHD);
        k_comb<<<NN / 32, 256>>>(ping, gcn_W + l * HH * HH, gcn_b + l * HH);
        ping ^= 1;
    }

    k_head<<<NN, HH>>>(ping, cls_W1, cls_b1, cls_W2, cls_b2, out_logits, out_h);
    k_mean<<<MBLK, HH>>>(ping);
    k_cont<<<1, HH>>>(con_W1, con_b1, con_W2, con_b2, out_c);
}

// round 2
// speedup vs baseline: 1.2240x; 1.2240x over previous
#include <cuda_runtime.h>
#include <math.h>

#define NN 4096
#define FF 64
#define HH 128
#define NHD 4
#define HD 32
#define LL 3
#define CC 7
#define MAXD 96
#define HHBLK 512   // k_hh blocks (8 nodes each)
#define MBLK 64     // mean partial blocks (64 rows each)

// ---------------- device scratch (no allocations allowed) ----------------
__device__ float g_h[2][NN * HH];
__device__ float g_hh[NN * HH];
__device__ float g_sup[NN * HH];
__device__ float g_att[NN * HH];
__device__ float g_ssrc[NN * NHD];
__device__ float g_sdst[NN * NHD];
__device__ float g_Spart[HH * HHBLK];   // [channel][block] — transposed for coalesced reduce
__device__ float g_S[HH];
__device__ int   g_cols[NN * MAXD];
__device__ int   g_cnt[NN];
__device__ float g_dinv[NN];
__device__ float g_mpart[MBLK * HH];

// ---------------- 1) fused: edge-list build (blocks 0..511) + encoder (blocks 512..2559)
__global__ void k_build_enc(const float* __restrict__ adj,
                            const float* __restrict__ x,
                            const float* __restrict__ W,
                            const float* __restrict__ b) {
    if (blockIdx.x < NN / 8) {
        // ---- adjacency scan: one warp per row ----
        int warp = (blockIdx.x * 256 + threadIdx.x) >> 5;
        int lane = threadIdx.x & 31;
        const float4* row = (const float4*)(adj + (size_t)warp * NN);
        int base = warp * MAXD;
        int cnt = 0;
        for (int c0 = 0; c0 < NN / 4; c0 += 32) {
            float4 v = row[c0 + lane];
            float vals[4] = {v.x, v.y, v.z, v.w};
#pragma unroll
            for (int k = 0; k < 4; k++) {
                unsigned m = __ballot_sync(0xffffffffu, vals[k] > 0.0f);
                if (vals[k] > 0.0f) {
                    int pos = cnt + __popc(m & ((1u << lane) - 1u));
                    if (pos < MAXD) g_cols[base + pos] = (c0 + lane) * 4 + k;
                }
                cnt += __popc(m);
            }
        }
        if (lane == 0) {
            if (cnt > MAXD) cnt = MAXD;
            g_cnt[warp] = cnt;
            g_dinv[warp] = rsqrtf((float)cnt + 1.0f);
        }
    } else {
        // ---- encoder: 2 nodes per block, 128 threads each ----
        __shared__ float xs[2][FF];
        int half = threadIdx.x >> 7;          // 0 or 1
        int c = threadIdx.x & 127;
        int n = (blockIdx.x - NN / 8) * 2 + half;
        if (c < FF) xs[half][c] = x[n * FF + c];
        __syncthreads();
        float acc = b[c];
#pragma unroll 16
        for (int k = 0; k < FF; k++) acc += xs[half][k] * W[k * HH + c];
        g_h[0][n * HH + c] = fmaxf(acc, 0.0f);
    }
}

// ---------------- 3) per-layer: hh = h @ W_attn + Wb ; s_src, s_dst ; S partials ----
__global__ void k_hh(int ping, const float* __restrict__ Wl,
                     const float* __restrict__ Wbl, const float* __restrict__ al) {
    __shared__ float hs[HH];
    const float* hin = g_h[ping];
    int c = threadIdx.x;
    int head = c >> 5, d = c & 31;
    float asrc = al[head * 2 * HD + d];
    float adst = al[head * 2 * HD + HD + d];
    float wb = Wbl[head * HD + d];
    const float* Wcol = Wl + head * HH * HD + d;  // stride HD over f
    float Sloc = 0.0f;
    int n0 = blockIdx.x * 8;
#pragma unroll 1
    for (int i = 0; i < 8; i++) {
        int n = n0 + i;
        __syncthreads();
        hs[c] = hin[n * HH + c];
        __syncthreads();
        float a0 = wb, a1 = 0.0f;
#pragma unroll 16
        for (int f = 0; f < HH; f += 2) {
            a0 += hs[f] * Wcol[f * HD];
            a1 += hs[f + 1] * Wcol[(f + 1) * HD];
        }
        float acc = a0 + a1;
        g_hh[n * HH + c] = acc;
        Sloc += acc;
        float vs = acc * asrc, vd = acc * adst;
#pragma unroll
        for (int off = 16; off; off >>= 1) {
            vs += __shfl_xor_sync(0xffffffffu, vs, off);
            vd += __shfl_xor_sync(0xffffffffu, vd, off);
        }
        if (d == 0) {
            g_ssrc[n * NHD + head] = vs;
            g_sdst[n * NHD + head] = vd;
        }
    }
    g_Spart[c * HHBLK + blockIdx.x] = Sloc;   // transposed: coalesced read in k_sred
}

// parallel reduce: one block per channel, fully coalesced
__global__ void k_sred() {
    __shared__ float sm[128];
    int c = blockIdx.x, t = threadIdx.x;
    const float* p = g_Spart + c * HHBLK;
    float s = p[t] + p[t + 128] + p[t + 256] + p[t + 384];
#pragma unroll
    for (int off = 16; off; off >>= 1) s += __shfl_xor_sync(0xffffffffu, s, off);
    if ((t & 31) == 0) sm[t >> 5] = s;
    __syncthreads();
    if (t == 0) g_S[c] = sm[0] + sm[1] + sm[2] + sm[3];
}

// ---------------- 4) per-layer sparse: GCN support + attention numer/denom ------
__global__ void k_sparse(int ping, const float* __restrict__ abl) {
    int n = blockIdx.x, c = threadIdx.x;
    int head = c >> 5;
    __shared__ int cols_s[MAXD];
    __shared__ float dinv_s[MAXD];
    __shared__ float w_s[MAXD * NHD];
    __shared__ float ss[NHD];
    const float* hin = g_h[ping];
    int E = g_cnt[n];
    if (c < NHD) ss[c] = g_ssrc[n * NHD + c] + abl[c];
    for (int e = c; e < E; e += HH) {
        int j = g_cols[n * MAXD + e];
        cols_s[e] = j;
        dinv_s[e] = g_dinv[j];
    }
    __syncthreads();
    for (int idx = c; idx < E * NHD; idx += HH) {
        int e = idx >> 2, h2 = idx & 3;
        w_s[idx] = expf(ss[h2] + g_sdst[cols_s[e] * NHD + h2]) - 1.0f;
    }
    __syncthreads();
    float di = g_dinv[n];
    float accg = di * hin[n * HH + c];
    float acca = g_S[c];
    float denom = (float)NN;
    for (int e = 0; e < E; e++) {
        int j = cols_s[e];
        accg += dinv_s[e] * hin[j * HH + c];
        float w = w_s[e * NHD + head];
        acca += w * g_hh[j * HH + c];
        denom += w;
    }
    g_sup[n * HH + c] = di * accg;
    g_att[n * HH + c] = acca / denom;
}

// ---------------- 5) per-layer combine: h' = relu(relu(sup@W + b) + att) -------
__global__ void k_comb(int ping, const float* __restrict__ Wl,
                       const float* __restrict__ bl) {
    __shared__ float Ws[32 * HH];   // 16KB W k-tile
    __shared__ float Ssm[32 * HH];  // 16KB support tile (32 rows)
    float* hout = g_h[ping ^ 1];
    int tid = threadIdx.x;
    int col = tid & 127, rg = tid >> 7;
    int r0 = blockIdx.x * 32;
    for (int i = tid; i < 32 * HH; i += 256) Ssm[i] = g_sup[r0 * HH + i];
    float acc[16];
#pragma unroll
    for (int i = 0; i < 16; i++) acc[i] = 0.0f;
    for (int kt = 0; kt < HH; kt += 32) {
        __syncthreads();
        for (int i = tid; i < 32 * HH; i += 256) Ws[i] = Wl[kt * HH + i];
        __syncthreads();
#pragma unroll 8
        for (int k = 0; k < 32; k++) {
            float w = Ws[k * HH + col];
#pragma unroll
            for (int i = 0; i < 16; i++)
                acc[i] += Ssm[(rg * 16 + i) * HH + kt + k] * w;
        }
    }
    float b = bl[col];
#pragma unroll
    for (int i = 0; i < 16; i++) {
        int r = r0 + rg * 16 + i;
        float v = fmaxf(acc[i] + b, 0.0f) + g_att[r * HH + col];
        hout[r * HH + col] = fmaxf(v, 0.0f);
    }
}

// ---------------- 6) fused: classifier head (blocks 0..4095) + mean partials ----
__global__ void k_head_mean(int ping, const float* __restrict__ W1, const float* __restrict__ b1,
                            const float* __restrict__ W2, const float* __restrict__ b2,
                            float* __restrict__ out_logits, float* __restrict__ out_h) {
    const float* hf = g_h[ping];
    int c = threadIdx.x;
    if (blockIdx.x < NN) {
        __shared__ float hs[HH];
        __shared__ float t1[64];
        int n = blockIdx.x;
        float hv = hf[n * HH + c];
        hs[c] = hv;
        out_h[n * HH + c] = hv;
        __syncthreads();
        if (c < 64) {
            float a = b1[c];
#pragma unroll 16
            for (int k = 0; k < HH; k++) a += hs[k] * W1[k * 64 + c];
            t1[c] = fmaxf(a, 0.0f);
        }
        __syncthreads();
        if (c < CC) {
            float a = b2[c];
#pragma unroll 16
            for (int k = 0; k < 64; k++) a += t1[k] * W2[k * CC + c];
            out_logits[n * CC + c] = a;
        }
    } else {
        int bb = blockIdx.x - NN;
        float s = 0.0f;
        for (int r = 0; r < NN / MBLK; r++) s += hf[(bb * (NN / MBLK) + r) * HH + c];
        g_mpart[bb * HH + c] = s;
    }
}

__global__ void k_cont(const float* __restrict__ W1, const float* __restrict__ b1,
                       const float* __restrict__ W2, const float* __restrict__ b2,
                       float* __restrict__ out_c) {
    __shared__ float ms[HH];
    __shared__ float t1[64];
    int c = threadIdx.x;
    float s = 0.0f;
    for (int b = 0; b < MBLK; b++) s += g_mpart[b * HH + c];
    ms[c] = s * (1.0f / (float)NN);
    __syncthreads();
    if (c < 64) {
        float a = b1[c];
#pragma unroll 16
        for (int k = 0; k < HH; k++) a += ms[k] * W1[k * 64 + c];
        t1[c] = fmaxf(a, 0.0f);
    }
    __syncthreads();
    if (c == 0) {
        float a = b2[0];
        for (int k = 0; k < 64; k++) a += t1[k] * W2[k];
        out_c[0] = a;
    }
}

extern "C" void kernel_launch(void* const* d_in, const int* in_sizes, int n_in,
                              void* d_out, int out_size) {
    const float* x      = (const float*)d_in[0];
    const float* adj    = (const float*)d_in[1];
    const float* enc_W  = (const float*)d_in[2];
    const float* enc_b  = (const float*)d_in[3];
    const float* gcn_W  = (const float*)d_in[4];   // [3,128,128]
    const float* gcn_b  = (const float*)d_in[5];   // [3,128]
    const float* attn_W = (const float*)d_in[6];   // [3,4,128,32]
    const float* attn_Wb= (const float*)d_in[7];   // [3,4,32]
    const float* attn_a = (const float*)d_in[8];   // [3,4,64]
    const float* attn_ab= (const float*)d_in[9];   // [3,4]
    const float* cls_W1 = (const float*)d_in[10];
    const float* cls_b1 = (const float*)d_in[11];
    const float* cls_W2 = (const float*)d_in[12];
    const float* cls_b2 = (const float*)d_in[13];
    const float* con_W1 = (const float*)d_in[14];
    const float* con_b1 = (const float*)d_in[15];
    const float* con_W2 = (const float*)d_in[16];
    const float* con_b2 = (const float*)d_in[17];

    float* out = (float*)d_out;
    float* out_logits = out;                 // [4096,7]
    float* out_h      = out + NN * CC;       // [4096,128]
    float* out_c      = out + NN * CC + NN * HH;  // [1]

    k_build_enc<<<NN / 8 + NN / 2, 256>>>(adj, x, enc_W, enc_b);

    int ping = 0;
    for (int l = 0; l < LL; l++) {
        k_hh<<<HHBLK, HH>>>(ping, attn_W + l * NHD * HH * HD,
                            attn_Wb + l * NHD * HD, attn_a + l * NHD * 2 * HD);
        k_sred<<<HH, HH>>>();
        k_sparse<<<NN, HH>>>(ping, attn_ab + l * NHD);
        k_comb<<<NN / 32, 256>>>(ping, gcn_W + l * HH * HH, gcn_b + l * HH);
        ping ^= 1;
    }

    k_head_mean<<<NN + MBLK, HH>>>(ping, cls_W1, cls_b1, cls_W2, cls_b2, out_logits, out_h);
    k_cont<<<1, HH>>>(con_W1, con_b1, con_W2, con_b2, out_c);
}

// round 3
// speedup vs baseline: 1.2524x; 1.0232x over previous
#include <cuda_runtime.h>
#include <math.h>

#define NN 4096
#define FF 64
#define HH 128
#define NHD 4
#define HD 32
#define LL 3
#define CC 7
#define MAXD 96
#define HHB 128     // k_hh blocks (32 rows each)
#define SPB (2*HHB) // S partials per channel
#define MBLK 64     // mean partial blocks

// ---------------- device scratch ----------------
__device__ float g_h[2][NN * HH];
__device__ float g_hh[NN * HH];
__device__ float g_sup[NN * HH];
__device__ float g_att[NN * HH];
__device__ float g_ssrc[NN * NHD];
__device__ float g_sdst[NN * NHD];
__device__ float g_Spart[HH * SPB];   // [channel][partial]
__device__ float g_S[HH];
__device__ int   g_cols[NN * MAXD];
__device__ int   g_cnt[NN];
__device__ float g_dinv[NN];
__device__ float g_mpart[MBLK * HH];

// ---------------- 1) fused: edge-list build + encoder ----------------
__global__ void k_build_enc(const float* __restrict__ adj,
                            const float* __restrict__ x,
                            const float* __restrict__ W,
                            const float* __restrict__ b) {
    if (blockIdx.x < NN / 8) {
        int warp = (blockIdx.x * 256 + threadIdx.x) >> 5;
        int lane = threadIdx.x & 31;
        const float4* row = (const float4*)(adj + (size_t)warp * NN);
        int base = warp * MAXD;
        int cnt = 0;
        for (int c0 = 0; c0 < NN / 4; c0 += 32) {
            float4 v = row[c0 + lane];
            float vals[4] = {v.x, v.y, v.z, v.w};
#pragma unroll
            for (int k = 0; k < 4; k++) {
                unsigned m = __ballot_sync(0xffffffffu, vals[k] > 0.0f);
                if (vals[k] > 0.0f) {
                    int pos = cnt + __popc(m & ((1u << lane) - 1u));
                    if (pos < MAXD) g_cols[base + pos] = (c0 + lane) * 4 + k;
                }
                cnt += __popc(m);
            }
        }
        if (lane == 0) {
            if (cnt > MAXD) cnt = MAXD;
            g_cnt[warp] = cnt;
            g_dinv[warp] = rsqrtf((float)cnt + 1.0f);
        }
    } else {
        __shared__ float xs[2][FF];
        int half = threadIdx.x >> 7;
        int c = threadIdx.x & 127;
        int n = (blockIdx.x - NN / 8) * 2 + half;
        if (c < FF) xs[half][c] = x[n * FF + c];
        __syncthreads();
        float acc = b[c];
#pragma unroll 16
        for (int k = 0; k < FF; k++) acc += xs[half][k] * W[k * HH + c];
        g_h[0][n * HH + c] = fmaxf(acc, 0.0f);
    }
}

// ---------------- 2) hh GEMM + epilogue (s_src, s_dst, S partials) ----------------
__global__ void k_hh(int ping, const float* __restrict__ Wl,
                     const float* __restrict__ Wbl, const float* __restrict__ al) {
    __shared__ float hs[32 * HH];
    __shared__ float Ws[32 * HH];
    const float* hin = g_h[ping];
    int tid = threadIdx.x;
    int col = tid & 127, rg = tid >> 7;
    int head = col >> 5, d = col & 31;
    int r0 = blockIdx.x * 32;
    for (int i = tid; i < 32 * HH; i += 256) hs[i] = hin[r0 * HH + i];
    float acc[16];
#pragma unroll
    for (int i = 0; i < 16; i++) acc[i] = 0.0f;
    for (int kt = 0; kt < HH; kt += 32) {
        __syncthreads();
        for (int i = tid; i < 32 * HH; i += 256) {
            int k = i >> 7, cc = i & 127;
            Ws[i] = Wl[(cc >> 5) * (HH * HD) + (kt + k) * HD + (cc & 31)];
        }
        __syncthreads();
#pragma unroll 8
        for (int k = 0; k < 32; k++) {
            float wv = Ws[k * HH + col];
#pragma unroll
            for (int i = 0; i < 16; i++)
                acc[i] += hs[(rg * 16 + i) * HH + kt + k] * wv;
        }
    }
    float wb = Wbl[col];
    float asrc = al[head * 64 + d];
    float adst = al[head * 64 + 32 + d];
    float Sloc = 0.0f;
#pragma unroll 1
    for (int i = 0; i < 16; i++) {
        int r = r0 + rg * 16 + i;
        float v = acc[i] + wb;
        g_hh[r * HH + col] = v;
        Sloc += v;
        float vs = v * asrc, vd = v * adst;
#pragma unroll
        for (int off = 16; off; off >>= 1) {
            vs += __shfl_xor_sync(0xffffffffu, vs, off);
            vd += __shfl_xor_sync(0xffffffffu, vd, off);
        }
        if (d == 0) {
            g_ssrc[r * NHD + head] = vs;
            g_sdst[r * NHD + head] = vd;
        }
    }
    g_Spart[col * SPB + blockIdx.x * 2 + rg] = Sloc;
}

// parallel reduce: one block per channel, coalesced
__global__ void k_sred() {
    __shared__ float sm[4];
    int c = blockIdx.x, t = threadIdx.x;
    const float* p = g_Spart + c * SPB;
    float s = p[t] + p[t + 128];
#pragma unroll
    for (int off = 16; off; off >>= 1) s += __shfl_xor_sync(0xffffffffu, s, off);
    if ((t & 31) == 0) sm[t >> 5] = s;
    __syncthreads();
    if (t == 0) g_S[c] = sm[0] + sm[1] + sm[2] + sm[3];
}

// ---------------- 3) sparse: one warp per node, float4 per lane ----------------
__global__ void k_sparse(int ping, const float* __restrict__ abl) {
    int tid = threadIdx.x;
    int w = tid >> 5, lane = tid & 31;
    int n = blockIdx.x * 4 + w;
    int head = lane >> 3;
    __shared__ int   cols_s[4][MAXD];
    __shared__ float dinv_s[4][MAXD];
    __shared__ float w_s[4][MAXD * NHD];
    __shared__ float ss4[4][NHD];
    const float4* hin4 = (const float4*)g_h[ping];
    const float4* hh4  = (const float4*)g_hh;
    int E = g_cnt[n];
    if (lane < NHD) ss4[w][lane] = g_ssrc[n * NHD + lane] + abl[lane];
    for (int e = lane; e < E; e += 32) {
        int j = g_cols[n * MAXD + e];
        cols_s[w][e] = j;
        dinv_s[w][e] = g_dinv[j];
    }
    __syncwarp();
    for (int idx = lane; idx < E * NHD; idx += 32) {
        int e = idx >> 2, h2 = idx & 3;
        w_s[w][idx] = expf(ss4[w][h2] + g_sdst[cols_s[w][e] * NHD + h2]) - 1.0f;
    }
    __syncwarp();
    float di = g_dinv[n];
    float4 hv = hin4[n * 32 + lane];
    float4 accg = make_float4(di * hv.x, di * hv.y, di * hv.z, di * hv.w);
    float4 acca = ((const float4*)g_S)[lane];
    float denom = (float)NN;
#pragma unroll 2
    for (int e = 0; e < E; e++) {
        int j = cols_s[w][e];
        float dj = dinv_s[w][e];
        float ww = w_s[w][e * NHD + head];
        float4 hj = hin4[j * 32 + lane];
        float4 gj = hh4[j * 32 + lane];
        accg.x += dj * hj.x; accg.y += dj * hj.y;
        accg.z += dj * hj.z; accg.w += dj * hj.w;
        acca.x += ww * gj.x; acca.y += ww * gj.y;
        acca.z += ww * gj.z; acca.w += ww * gj.w;
        denom += ww;
    }
    float inv = 1.0f / denom;
    ((float4*)g_sup)[n * 32 + lane] =
        make_float4(di * accg.x, di * accg.y, di * accg.z, di * accg.w);
    ((float4*)g_att)[n * 32 + lane] =
        make_float4(acca.x * inv, acca.y * inv, acca.z * inv, acca.w * inv);
}

// ---------------- 4) combine GEMM: h' = relu(relu(sup@W + b) + att) ----------------
__global__ void k_comb(int ping, const float* __restrict__ Wl,
                       const float* __restrict__ bl) {
    __shared__ float Ws[32 * HH];
    __shared__ float Ssm[32 * HH];
    float* hout = g_h[ping ^ 1];
    int tid = threadIdx.x;
    int col = tid & 127, rg = tid >> 7;
    int r0 = blockIdx.x * 32;
    for (int i = tid; i < 32 * HH; i += 256) Ssm[i] = g_sup[r0 * HH + i];
    float acc[16];
#pragma unroll
    for (int i = 0; i < 16; i++) acc[i] = 0.0f;
    for (int kt = 0; kt < HH; kt += 32) {
        __syncthreads();
        for (int i = tid; i < 32 * HH; i += 256) Ws[i] = Wl[kt * HH + i];
        __syncthreads();
#pragma unroll 8
        for (int k = 0; k < 32; k++) {
            float w = Ws[k * HH + col];
#pragma unroll
            for (int i = 0; i < 16; i++)
                acc[i] += Ssm[(rg * 16 + i) * HH + kt + k] * w;
        }
    }
    float b = bl[col];
#pragma unroll
    for (int i = 0; i < 16; i++) {
        int r = r0 + rg * 16 + i;
        float v = fmaxf(acc[i] + b, 0.0f) + g_att[r * HH + col];
        hout[r * HH + col] = fmaxf(v, 0.0f);
    }
}

// ---------------- 5) fused classifier head + mean partials ----------------
__global__ void k_head_mean(int ping, const float* __restrict__ W1, const float* __restrict__ b1,
                            const float* __restrict__ W2, const float* __restrict__ b2,
                            float* __restrict__ out_logits, float* __restrict__ out_h) {
    const float* hf = g_h[ping];
    int c = threadIdx.x;
    if (blockIdx.x < NN) {
        __shared__ float hs[HH];
        __shared__ float t1[64];
        int n = blockIdx.x;
        float hv = hf[n * HH + c];
        hs[c] = hv;
        out_h[n * HH + c] = hv;
        __syncthreads();
        if (c < 64) {
            float a = b1[c];
#pragma unroll 16
            for (int k = 0; k < HH; k++) a += hs[k] * W1[k * 64 + c];
            t1[c] = fmaxf(a, 0.0f);
        }
        __syncthreads();
        if (c < CC) {
            float a = b2[c];
#pragma unroll 16
            for (int k = 0; k < 64; k++) a += t1[k] * W2[k * CC + c];
            out_logits[n * CC + c] = a;
        }
    } else {
        int bb = blockIdx.x - NN;
        float s = 0.0f;
        for (int r = 0; r < NN / MBLK; r++) s += hf[(bb * (NN / MBLK) + r) * HH + c];
        g_mpart[bb * HH + c] = s;
    }
}

__global__ void k_cont(const float* __restrict__ W1, const float* __restrict__ b1,
                       const float* __restrict__ W2, const float* __restrict__ b2,
                       float* __restrict__ out_c) {
    __shared__ float ms[HH];
    __shared__ float t1[64];
    int c = threadIdx.x;
    float s = 0.0f;
    for (int b = 0; b < MBLK; b++) s += g_mpart[b * HH + c];
    ms[c] = s * (1.0f / (float)NN);
    __syncthreads();
    if (c < 64) {
        float a = b1[c];
#pragma unroll 16
        for (int k = 0; k < HH; k++) a += ms[k] * W1[k * 64 + c];
        t1[c] = fmaxf(a, 0.0f);
    }
    __syncthreads();
    if (c == 0) {
        float a = b2[0];
        for (int k = 0; k < 64; k++) a += t1[k] * W2[k];
        out_c[0] = a;
    }
}

extern "C" void kernel_launch(void* const* d_in, const int* in_sizes, int n_in,
                              void* d_out, int out_size) {
    const float* x      = (const float*)d_in[0];
    const float* adj    = (const float*)d_in[1];
    const float* enc_W  = (const float*)d_in[2];
    const float* enc_b  = (const float*)d_in[3];
    const float* gcn_W  = (const float*)d_in[4];
    const float* gcn_b  = (const float*)d_in[5];
    const float* attn_W = (const float*)d_in[6];
    const float* attn_Wb= (const float*)d_in[7];
    const float* attn_a = (const float*)d_in[8];
    const float* attn_ab= (const float*)d_in[9];
    const float* cls_W1 = (const float*)d_in[10];
    const float* cls_b1 = (const float*)d_in[11];
    const float* cls_W2 = (const float*)d_in[12];
    const float* cls_b2 = (const float*)d_in[13];
    const float* con_W1 = (const float*)d_in[14];
    const float* con_b1 = (const float*)d_in[15];
    const float* con_W2 = (const float*)d_in[16];
    const float* con_b2 = (const float*)d_in[17];

    float* out = (float*)d_out;
    float* out_logits = out;
    float* out_h      = out + NN * CC;
    float* out_c      = out + NN * CC + NN * HH;

    k_build_enc<<<NN / 8 + NN / 2, 256>>>(adj, x, enc_W, enc_b);

    int ping = 0;
    for (int l = 0; l < LL; l++) {
        k_hh<<<HHB, 256>>>(ping, attn_W + l * NHD * HH * HD,
                           attn_Wb + l * NHD * HD, attn_a + l * NHD * 2 * HD);
        k_sred<<<HH, HH>>>();
        k_sparse<<<NN / 4, HH>>>(ping, attn_ab + l * NHD);
        k_comb<<<NN / 32, 256>>>(ping, gcn_W + l * HH * HH, gcn_b + l * HH);
        ping ^= 1;
    }

    k_head_mean<<<NN + MBLK, HH>>>(ping, cls_W1, cls_b1, cls_W2, cls_b2, out_logits, out_h);
    k_cont<<<1, HH>>>(con_W1, con_b1, con_W2, con_b2, out_c);
}